// round 1
// baseline (speedup 1.0000x reference)
#include <cuda_runtime.h>

#define P_ 2
#define B_ 96
#define A_ 32
#define N_ 3072        // B_*A_
#define NT_ 24
#define MD_ 4
#define MA_ 4
#define NPOL_ 8
#define C_LK 0.0897935610625833f

// Scratch (no allocations allowed)
__device__ float4 g_atom[P_*N_];       // x,y,z, rj
__device__ float  g_vol[P_*N_];        // volj if heavy else 0
__device__ double g_partial[P_*B_*2];  // per-(pose,block) partial sums

__device__ __forceinline__ int clampA(int v){ return min(max(v,0), A_-1); }

// ---------------------------------------------------------------------------
// Prep: pack per-atom data. Fold the "heavy" mask into vol (vol multiplies
// lk_iso linearly, so vol=0 for hydrogens reproduces the mask exactly).
// ---------------------------------------------------------------------------
__global__ void prep_kernel(const float* __restrict__ coords,
                            const int*   __restrict__ btype,
                            const int*   __restrict__ is_h,
                            const float* __restrict__ lkp)
{
    int idx = blockIdx.x*blockDim.x + threadIdx.x;
    if (idx >= P_*N_) return;
    int p = idx / N_;
    int j = idx - p*N_;
    int b = j >> 5;
    int a = j & 31;
    int bt = btype[p*B_+b];
    float rj  = lkp[(bt*A_+a)*4+0];
    float vol = lkp[(bt*A_+a)*4+3];
    g_atom[idx] = make_float4(coords[idx*3], coords[idx*3+1], coords[idx*3+2], rj);
    g_vol[idx]  = (is_h[bt*A_+a]==0) ? vol : 0.0f;
}

// ---------------------------------------------------------------------------
// Main: one CTA per (pose, block). Setup phase builds the compacted polar
// list (waters + params) in shared; main phase loops all N_ atoms.
// ---------------------------------------------------------------------------
__global__ void __launch_bounds__(256) main_kernel(
    const float* __restrict__ coords,
    const int*   __restrict__ btype,
    const int*   __restrict__ minsep,
    const int*   __restrict__ bonds,     // (NT,A,2)
    const int*   __restrict__ ranges,    // (NT,A,2)
    const int*   __restrict__ n_donH,
    const int*   __restrict__ n_acc,
    const int*   __restrict__ donH_i,
    const int*   __restrict__ don_hvy_i,
    const int*   __restrict__ acc_i_arr,
    const int*   __restrict__ hyb_arr,
    const float* __restrict__ lkp,
    const int*   __restrict__ pathd,     // (NT,A,A)
    const float* __restrict__ lkgp,
    const float* __restrict__ wgp,
    const float* __restrict__ sp2t,
    const float* __restrict__ sp3t,
    const float* __restrict__ ringt)
{
    __shared__ float4 st_pol[NPOL_], st_w0[NPOL_], st_w1[NPOL_];
    __shared__ int    st_a[NPOL_], st_act[NPOL_];
    __shared__ float4 s_pol[NPOL_], s_w0[NPOL_], s_w1[NPOL_];
    __shared__ int    s_arow[NPOL_];
    __shared__ int    s_npol;
    __shared__ unsigned char s_sepok[B_];
    __shared__ double s_red[8][2];

    int p   = blockIdx.x / B_;
    int b   = blockIdx.x - p*B_;
    int tid = threadIdx.x;
    int bt  = btype[p*B_+b];
    const float* cblk = coords + (size_t)(p*N_ + b*A_)*3;

    // ---- water generation for the 8 polar slots (threads 0..7) ----
    if (tid < NPOL_) {
        float wdist = wgp[0], wang = wgp[1];
        int active = 0, ai = 0;
        float xp0=0,xp1=0,xp2=0,w00=0,w01=0,w02=0,w10=0,w11=0,w12=0;
        if (tid < MD_) {                       // donor slot
            int i = tid;
            if (i < n_donH[bt]) {
                active = 1;
                ai      = clampA(don_hvy_i[bt*MD_+i]);
                int hi  = clampA(donH_i[bt*MD_+i]);
                float hx=cblk[ai*3], hy=cblk[ai*3+1], hz=cblk[ai*3+2];
                float Hx=cblk[hi*3], Hy=cblk[hi*3+1], Hz=cblk[hi*3+2];
                float dx=Hx-hx, dy=Hy-hy, dz=Hz-hz;
                float inv = rsqrtf(dx*dx+dy*dy+dz*dz + 1e-12f);
                xp0=hx; xp1=hy; xp2=hz;
                w00=hx+wdist*inv*dx; w01=hy+wdist*inv*dy; w02=hz+wdist*inv*dz;
                // water slot 1 is masked for donors: sentinel far away
                // (ref uses d2w=1e9 for masked; min() picks water0 either way)
                w10=1e5f; w11=1e5f; w12=1e5f;
            }
        } else {                               // acceptor slot
            int i = tid - MD_;
            if (i < n_acc[bt]) {
                active = 1;
                ai        = clampA(acc_i_arr[bt*MA_+i]);
                int r0    = clampA(ranges[(bt*A_+ai)*2]);
                int base  = clampA(bonds [(bt*A_+r0)*2+1]);
                int r1    = clampA(ranges[(bt*A_+base)*2]);
                int base2 = clampA(bonds [(bt*A_+r1)*2+1]);
                float cx=cblk[ai*3],   cy=cblk[ai*3+1],   cz=cblk[ai*3+2];
                float bx=cblk[base*3], by=cblk[base*3+1], bz=cblk[base*3+2];
                float ax=cblk[base2*3],ay=cblk[base2*3+1],az=cblk[base2*3+2];
                float e1x=cx-bx, e1y=cy-by, e1z=cz-bz;
                float inv = rsqrtf(e1x*e1x+e1y*e1y+e1z*e1z + 1e-12f);
                e1x*=inv; e1y*=inv; e1z*=inv;
                float ux=bx-ax, uy=by-ay, uz=bz-az;
                float nx=uy*e1z-uz*e1y, ny=uz*e1x-ux*e1z, nz=ux*e1y-uy*e1x;
                inv = rsqrtf(nx*nx+ny*ny+nz*nz + 1e-12f);
                nx*=inv; ny*=inv; nz*=inv;
                float e2x=ny*e1z-nz*e1y, e2y=nz*e1x-nx*e1z, e2z=nx*e1y-ny*e1x;
                int hyb = hyb_arr[bt*MA_+i];
                float chi0, chi1;
                if      (hyb == 0) { chi0=sp2t[0];  chi1=sp2t[1];  }
                else if (hyb == 1) { chi0=sp3t[0];  chi1=sp3t[1];  }
                else               { chi0=ringt[0]; chi1=ringt[1]; }
                float ct=cosf(wang), st=sinf(wang);
                float a1 = -wdist*ct;
                float b0 = wdist*st*cosf(chi0), c0 = wdist*st*sinf(chi0);
                float b1 = wdist*st*cosf(chi1), c1 = wdist*st*sinf(chi1);
                xp0=cx; xp1=cy; xp2=cz;
                w00 = cx + a1*e1x + b0*e2x + c0*nx;
                w01 = cy + a1*e1y + b0*e2y + c0*ny;
                w02 = cz + a1*e1z + b0*e2z + c0*nz;
                w10 = cx + a1*e1x + b1*e2x + c1*nx;
                w11 = cy + a1*e1y + b1*e2y + c1*ny;
                w12 = cz + a1*e1z + b1*e2z + c1*nz;
            }
        }
        st_act[tid] = active;
        if (active) {
            float ri  = lkp[(bt*A_+ai)*4+0];
            float dgi = lkp[(bt*A_+ai)*4+1];
            float lam = lkp[(bt*A_+ai)*4+2];
            st_pol[tid] = make_float4(xp0, xp1, xp2, ri);
            st_w0[tid]  = make_float4(w00, w01, w02, C_LK*dgi/lam);
            st_w1[tid]  = make_float4(w10, w11, w12, 1.0f/lam);
            st_a[tid]   = ai*A_;
        }
    }
    // inter-block separation mask row (path handles the same-block case)
    for (int t = tid; t < B_; t += blockDim.x)
        s_sepok[t] = (minsep[(p*B_+b)*B_+t] >= 4) ? 1 : 0;
    __syncthreads();
    if (tid == 0) {                         // compact active polar slots
        int n = 0;
        for (int t = 0; t < NPOL_; t++) if (st_act[t]) {
            s_pol[n]=st_pol[t]; s_w0[n]=st_w0[t]; s_w1[n]=st_w1[t]; s_arow[n]=st_a[t];
            n++;
        }
        s_npol = n;
    }
    __syncthreads();

    float cutoff  = lkgp[0];
    float cutoff2 = cutoff*cutoff;
    float ramp2   = lkgp[1];
    float d2lr    = lkgp[2] + ramp2;
    float invramp = 1.0f/ramp2;

    const float4* abase = g_atom + p*N_;
    const float*  vbase = g_vol  + p*N_;
    const int*    prow  = pathd + bt*A_*A_;
    int np = s_npol;

    float sum0 = 0.f, sum1 = 0.f;
    for (int j = tid; j < N_; j += 256) {
        float vol = vbase[j];
        if (vol == 0.f) continue;           // hydrogen: lk_iso == 0 always
        float4 aj = abase[j];
        int  bj   = j >> 5;
        bool same = (bj == b);
        bool okI  = s_sepok[bj];
        int  ajA  = j & 31;
        #pragma unroll 1
        for (int k = 0; k < np; k++) {
            float4 pol = s_pol[k];
            float dx = pol.x-aj.x, dy = pol.y-aj.y, dz = pol.z-aj.z;
            float d2 = fmaxf(dx*dx + dy*dy + dz*dz, 0.01f);
            if (d2 >= cutoff2) continue;    // ~97% of pairs exit here
            bool ok = same ? (prow[s_arow[k]+ajA] >= 4) : okI;
            if (!ok) continue;
            float4 w0 = s_w0[k];
            float4 w1 = s_w1[k];
            float d  = sqrtf(d2);
            float xq = (d - pol.w - aj.w) * w1.w;        // (d-ri-rj)/lam
            float lk = __fdividef(w0.w * vol * __expf(-xq*xq), d2);
            float a0x=w0.x-aj.x, a0y=w0.y-aj.y, a0z=w0.z-aj.z;
            float dw0 = a0x*a0x + a0y*a0y + a0z*a0z;
            float a1x=w1.x-aj.x, a1y=w1.y-aj.y, a1z=w1.z-aj.z;
            float dw1 = a1x*a1x + a1y*a1y + a1z*a1z;
            float dm = fminf(dw0, dw1);
            float wt = __saturatef((d2lr - dm) * invramp);
            float fr = wt*wt*(3.f - 2.f*wt);
            sum0 += lk;
            sum1 += lk*fr;
        }
    }

    // deterministic block reduction (fp64 from here on)
    double d0 = sum0, d1 = sum1;
    for (int off = 16; off; off >>= 1) {
        d0 += __shfl_xor_sync(0xffffffffu, d0, off);
        d1 += __shfl_xor_sync(0xffffffffu, d1, off);
    }
    int warp = tid >> 5;
    if ((tid & 31) == 0) { s_red[warp][0]=d0; s_red[warp][1]=d1; }
    __syncthreads();
    if (tid == 0) {
        double a=0, c=0;
        for (int w = 0; w < 8; w++) { a+=s_red[w][0]; c+=s_red[w][1]; }
        g_partial[blockIdx.x*2]   = a;
        g_partial[blockIdx.x*2+1] = c;
    }
}

// ---------------------------------------------------------------------------
// Final fixed-order reduce -> out[2][P]  (row0: sum lk_iso, row1: sum lk*frac)
// ---------------------------------------------------------------------------
__global__ void reduce_kernel(float* __restrict__ out) {
    __shared__ double s0[P_*B_], s1[P_*B_];
    int t = threadIdx.x;
    if (t < P_*B_) { s0[t]=g_partial[t*2]; s1[t]=g_partial[t*2+1]; }
    __syncthreads();
    if (t < P_) {
        double a=0, c=0;
        for (int i = 0; i < B_; i++) { a += s0[t*B_+i]; c += s1[t*B_+i]; }
        out[t]     = (float)a;
        out[P_+t]  = (float)c;
    }
}

extern "C" void kernel_launch(void* const* d_in, const int* in_sizes, int n_in,
                              void* d_out, int out_size) {
    const float* coords  = (const float*)d_in[0];
    const int*   btype   = (const int*)  d_in[1];
    const int*   minsep  = (const int*)  d_in[2];
    // d_in[3] = bt_n_atoms (unused: all blocks have A_ atoms)
    const int*   bonds   = (const int*)  d_in[4];
    const int*   ranges  = (const int*)  d_in[5];
    const int*   n_donH  = (const int*)  d_in[6];
    const int*   n_acc   = (const int*)  d_in[7];
    const int*   donH_i  = (const int*)  d_in[8];
    const int*   don_hvy = (const int*)  d_in[9];
    const int*   acc_i   = (const int*)  d_in[10];
    const int*   hyb     = (const int*)  d_in[11];
    const int*   is_h    = (const int*)  d_in[12];
    const float* lkp     = (const float*)d_in[13];
    const int*   pathd   = (const int*)  d_in[14];
    const float* lkgp    = (const float*)d_in[15];
    const float* wgp     = (const float*)d_in[16];
    const float* sp2     = (const float*)d_in[17];
    const float* sp3     = (const float*)d_in[18];
    const float* ringt   = (const float*)d_in[19];

    prep_kernel<<<(P_*N_+255)/256, 256>>>(coords, btype, is_h, lkp);
    main_kernel<<<P_*B_, 256>>>(coords, btype, minsep, bonds, ranges,
                                n_donH, n_acc, donH_i, don_hvy, acc_i, hyb,
                                lkp, pathd, lkgp, wgp, sp2, sp3, ringt);
    reduce_kernel<<<1, 256>>>((float*)d_out);
}

// round 2
// speedup vs baseline: 1.1250x; 1.1250x over previous
#include <cuda_runtime.h>

#define P_ 2
#define B_ 96
#define A_ 32
#define N_ 3072        // B_*A_
#define NT_ 24
#define MD_ 4
#define MA_ 4
#define NPOL_ 8
#define CH_ 2          // j-range chunks per (pose,block)
#define TPB_ 384
#define JPT_ ((N_/CH_)/TPB_)   // 4 atoms per thread
#define C_LK 0.0897935610625833f

// Scratch (no allocations allowed)
__device__ double g_partial[P_*B_*CH_*2];
__device__ unsigned int g_done;   // zero-init; last CTA resets -> graph-replay safe

__device__ __forceinline__ int clampA(int v){ return min(max(v,0), A_-1); }

__global__ void __launch_bounds__(TPB_) lkball_kernel(
    const float* __restrict__ coords,
    const int*   __restrict__ btype,
    const int*   __restrict__ minsep,
    const int*   __restrict__ bonds,     // (NT,A,2)
    const int*   __restrict__ ranges,    // (NT,A,2)
    const int*   __restrict__ n_donH,
    const int*   __restrict__ n_acc,
    const int*   __restrict__ donH_i,
    const int*   __restrict__ don_hvy_i,
    const int*   __restrict__ acc_i_arr,
    const int*   __restrict__ hyb_arr,
    const float* __restrict__ lkp,       // (NT,A,4) -> float4 aligned
    const int*   __restrict__ is_h,      // (NT,A)
    const int*   __restrict__ pathd,     // (NT,A,A)
    const float* __restrict__ lkgp,
    const float* __restrict__ wgp,
    const float* __restrict__ sp2t,
    const float* __restrict__ sp3t,
    const float* __restrict__ ringt,
    float*       __restrict__ out)
{
    __shared__ float4 st_pol[NPOL_], st_w0[NPOL_], st_w1[NPOL_];
    __shared__ int    st_a[NPOL_], st_act[NPOL_];
    __shared__ float4 s_pol[NPOL_], s_w0[NPOL_], s_w1[NPOL_];
    __shared__ int    s_arow[NPOL_];
    __shared__ unsigned char s_sepok[B_];
    __shared__ short  s_bt[B_];
    __shared__ double s_red[TPB_/32][2];

    int cta = blockIdx.x;
    int c   = cta & (CH_-1);
    int pb  = cta >> 1;            // CH_==2
    int p   = pb / B_;
    int b   = pb - p*B_;
    int tid = threadIdx.x;
    int bt  = btype[p*B_+b];
    const float* cblk = coords + (size_t)(p*N_ + b*A_)*3;
    const float4* lkp4 = (const float4*)lkp;

    // ---- water generation for the 8 polar slots (threads 0..7) ----
    if (tid < NPOL_) {
        float wdist = wgp[0], wang = wgp[1];
        int active = 0, ai = 0;
        float xp0=0,xp1=0,xp2=0,w00=0,w01=0,w02=0,w10=0,w11=0,w12=0;
        if (tid < MD_) {                       // donor slot
            int i = tid;
            if (i < n_donH[bt]) {
                active = 1;
                ai      = clampA(don_hvy_i[bt*MD_+i]);
                int hi  = clampA(donH_i[bt*MD_+i]);
                float hx=cblk[ai*3], hy=cblk[ai*3+1], hz=cblk[ai*3+2];
                float Hx=cblk[hi*3], Hy=cblk[hi*3+1], Hz=cblk[hi*3+2];
                float dx=Hx-hx, dy=Hy-hy, dz=Hz-hz;
                float inv = rsqrtf(dx*dx+dy*dy+dz*dz + 1e-12f);
                xp0=hx; xp1=hy; xp2=hz;
                w00=hx+wdist*inv*dx; w01=hy+wdist*inv*dy; w02=hz+wdist*inv*dz;
                w10=1e5f; w11=1e5f; w12=1e5f;      // masked water -> far sentinel
            }
        } else {                               // acceptor slot
            int i = tid - MD_;
            if (i < n_acc[bt]) {
                active = 1;
                ai        = clampA(acc_i_arr[bt*MA_+i]);
                int r0    = clampA(ranges[(bt*A_+ai)*2]);
                int base  = clampA(bonds [(bt*A_+r0)*2+1]);
                int r1    = clampA(ranges[(bt*A_+base)*2]);
                int base2 = clampA(bonds [(bt*A_+r1)*2+1]);
                float cx=cblk[ai*3],   cy=cblk[ai*3+1],   cz=cblk[ai*3+2];
                float bx=cblk[base*3], by=cblk[base*3+1], bz=cblk[base*3+2];
                float ax=cblk[base2*3],ay=cblk[base2*3+1],az=cblk[base2*3+2];
                float e1x=cx-bx, e1y=cy-by, e1z=cz-bz;
                float inv = rsqrtf(e1x*e1x+e1y*e1y+e1z*e1z + 1e-12f);
                e1x*=inv; e1y*=inv; e1z*=inv;
                float ux=bx-ax, uy=by-ay, uz=bz-az;
                float nx=uy*e1z-uz*e1y, ny=uz*e1x-ux*e1z, nz=ux*e1y-uy*e1x;
                inv = rsqrtf(nx*nx+ny*ny+nz*nz + 1e-12f);
                nx*=inv; ny*=inv; nz*=inv;
                float e2x=ny*e1z-nz*e1y, e2y=nz*e1x-nx*e1z, e2z=nx*e1y-ny*e1x;
                int hyb = hyb_arr[bt*MA_+i];
                float chi0, chi1;
                if      (hyb == 0) { chi0=sp2t[0];  chi1=sp2t[1];  }
                else if (hyb == 1) { chi0=sp3t[0];  chi1=sp3t[1];  }
                else               { chi0=ringt[0]; chi1=ringt[1]; }
                float ct=cosf(wang), st=sinf(wang);
                float a1 = -wdist*ct;
                float b0 = wdist*st*cosf(chi0), c0 = wdist*st*sinf(chi0);
                float b1 = wdist*st*cosf(chi1), c1 = wdist*st*sinf(chi1);
                xp0=cx; xp1=cy; xp2=cz;
                w00 = cx + a1*e1x + b0*e2x + c0*nx;
                w01 = cy + a1*e1y + b0*e2y + c0*ny;
                w02 = cz + a1*e1z + b0*e2z + c0*nz;
                w10 = cx + a1*e1x + b1*e2x + c1*nx;
                w11 = cy + a1*e1y + b1*e2y + c1*ny;
                w12 = cz + a1*e1z + b1*e2z + c1*nz;
            }
        }
        st_act[tid] = active;
        if (active) {
            float4 q = lkp4[bt*A_+ai];           // ri,dgi,lam,vol
            st_pol[tid] = make_float4(xp0, xp1, xp2, q.x);
            st_w0[tid]  = make_float4(w00, w01, w02, C_LK*q.y/q.z);
            st_w1[tid]  = make_float4(w10, w11, w12, 1.0f/q.z);
            st_a[tid]   = ai*A_;
        }
    }
    // inter-block sep mask + block types for this pose
    if (tid < B_) {
        s_sepok[tid] = (minsep[(p*B_+b)*B_+tid] >= 4) ? 1 : 0;
        s_bt[tid]    = (short)btype[p*B_+tid];
    }
    __syncthreads();
    if (tid == 0) {                         // compact + pad to 8 with dummies
        int n = 0;
        for (int t = 0; t < NPOL_; t++) if (st_act[t]) {
            s_pol[n]=st_pol[t]; s_w0[n]=st_w0[t]; s_w1[n]=st_w1[t]; s_arow[n]=st_a[t];
            n++;
        }
        for (; n < NPOL_; n++) {
            s_pol[n]=make_float4(1e6f,1e6f,1e6f,0.f);   // never passes cutoff
            s_w0[n]=make_float4(0,0,0,0); s_w1[n]=make_float4(0,0,0,1.f);
            s_arow[n]=0;
        }
    }
    __syncthreads();

    // hoist the 8 polar positions into registers
    float px[NPOL_], py[NPOL_], pz[NPOL_], pri[NPOL_];
    #pragma unroll
    for (int k = 0; k < NPOL_; k++) {
        float4 q = s_pol[k];
        px[k]=q.x; py[k]=q.y; pz[k]=q.z; pri[k]=q.w;
    }

    float cutoff2 = lkgp[0]*lkgp[0];
    float ramp2   = lkgp[1];
    float d2lr    = lkgp[2] + ramp2;
    float invramp = 1.0f/ramp2;

    const float* cp   = coords + (size_t)p*N_*3;
    const int*   prow = pathd + bt*A_*A_;

    float sum0 = 0.f, sum1 = 0.f;
    int jbase = c*(N_/CH_) + tid;
    #pragma unroll
    for (int it = 0; it < JPT_; it++) {
        int j = jbase + it*TPB_;
        float ax = cp[3*j], ay = cp[3*j+1], az = cp[3*j+2];
        float d2[NPOL_];
        #pragma unroll
        for (int k = 0; k < NPOL_; k++) {
            float dx = px[k]-ax, dy = py[k]-ay, dz = pz[k]-az;
            d2[k] = dx*dx + dy*dy + dz*dz;
        }
        float m01 = fminf(d2[0],d2[1]), m23 = fminf(d2[2],d2[3]);
        float m45 = fminf(d2[4],d2[5]), m67 = fminf(d2[6],d2[7]);
        float mall = fminf(fminf(m01,m23), fminf(m45,m67));
        if (mall < cutoff2) {                       // ~14% of j enter (warp-wide more)
            int bj  = j >> 5;
            int ajA = j & 31;
            int btj = s_bt[bj];
            bool heavy = (is_h[btj*A_+ajA] == 0);
            if (heavy) {
                float4 q = lkp4[btj*A_+ajA];        // rj = q.x, vol = q.w
                float rj = q.x, vol = q.w;
                bool same = (bj == b);
                bool okI  = s_sepok[bj];
                #pragma unroll
                for (int k = 0; k < NPOL_; k++) {
                    if (d2[k] < cutoff2) {
                        bool ok = same ? (prow[s_arow[k]+ajA] >= 4) : okI;
                        if (ok) {
                            float4 w0 = s_w0[k];
                            float4 w1 = s_w1[k];
                            float d2c = fmaxf(d2[k], 0.01f);
                            float d   = sqrtf(d2c);
                            float xq  = (d - pri[k] - rj) * w1.w;
                            float lk  = __fdividef(w0.w * vol * __expf(-xq*xq), d2c);
                            float a0x=w0.x-ax, a0y=w0.y-ay, a0z=w0.z-az;
                            float dw0 = a0x*a0x + a0y*a0y + a0z*a0z;
                            float a1x=w1.x-ax, a1y=w1.y-ay, a1z=w1.z-az;
                            float dw1 = a1x*a1x + a1y*a1y + a1z*a1z;
                            float dm = fminf(dw0, dw1);
                            float wt = __saturatef((d2lr - dm) * invramp);
                            float fr = wt*wt*(3.f - 2.f*wt);
                            sum0 += lk;
                            sum1 += lk*fr;
                        }
                    }
                }
            }
        }
    }

    // deterministic CTA reduction (fp64)
    double d0 = sum0, d1 = sum1;
    for (int off = 16; off; off >>= 1) {
        d0 += __shfl_xor_sync(0xffffffffu, d0, off);
        d1 += __shfl_xor_sync(0xffffffffu, d1, off);
    }
    int warp = tid >> 5;
    if ((tid & 31) == 0) { s_red[warp][0]=d0; s_red[warp][1]=d1; }
    __syncthreads();
    if (tid == 0) {
        double a=0, cc=0;
        #pragma unroll
        for (int w = 0; w < TPB_/32; w++) { a+=s_red[w][0]; cc+=s_red[w][1]; }
        g_partial[cta*2]   = a;
        g_partial[cta*2+1] = cc;
    }

    // ---- last-CTA final reduce (fixed-order tree -> deterministic) ----
    __shared__ bool s_last;
    __threadfence();
    if (tid == 0)
        s_last = (atomicAdd(&g_done, 1u) == (unsigned)(gridDim.x - 1));
    __syncthreads();
    if (!s_last) return;

    __shared__ double r0[P_*B_*CH_], r1[P_*B_*CH_];   // 384 each
    r0[tid] = g_partial[tid*2];
    r1[tid] = g_partial[tid*2+1];
    __syncthreads();
    // per-pose segments of 192: tree 96..3, then serial 3
    int seg = (tid < 192) ? 0 : 192;
    int loc = tid - seg;
    #pragma unroll
    for (int s = 96; s >= 3; s >>= 1) {
        if (loc < s) { r0[tid] += r0[tid+s]; r1[tid] += r1[tid+s]; }
        __syncthreads();
    }
    if (tid == 0) {
        out[0]    = (float)(r0[0]   + r0[1]   + r0[2]);
        out[P_+0] = (float)(r1[0]   + r1[1]   + r1[2]);
        out[1]    = (float)(r0[192] + r0[193] + r0[194]);
        out[P_+1] = (float)(r1[192] + r1[193] + r1[194]);
        g_done = 0;                      // reset for next graph replay
    }
}

extern "C" void kernel_launch(void* const* d_in, const int* in_sizes, int n_in,
                              void* d_out, int out_size) {
    const float* coords  = (const float*)d_in[0];
    const int*   btype   = (const int*)  d_in[1];
    const int*   minsep  = (const int*)  d_in[2];
    // d_in[3] = bt_n_atoms (unused: all blocks have A_ atoms)
    const int*   bonds   = (const int*)  d_in[4];
    const int*   ranges  = (const int*)  d_in[5];
    const int*   n_donH  = (const int*)  d_in[6];
    const int*   n_acc   = (const int*)  d_in[7];
    const int*   donH_i  = (const int*)  d_in[8];
    const int*   don_hvy = (const int*)  d_in[9];
    const int*   acc_i   = (const int*)  d_in[10];
    const int*   hyb     = (const int*)  d_in[11];
    const int*   is_h    = (const int*)  d_in[12];
    const float* lkp     = (const float*)d_in[13];
    const int*   pathd   = (const int*)  d_in[14];
    const float* lkgp    = (const float*)d_in[15];
    const float* wgp     = (const float*)d_in[16];
    const float* sp2     = (const float*)d_in[17];
    const float* sp3     = (const float*)d_in[18];
    const float* ringt   = (const float*)d_in[19];

    lkball_kernel<<<P_*B_*CH_, TPB_>>>(coords, btype, minsep, bonds, ranges,
                                       n_donH, n_acc, donH_i, don_hvy, acc_i, hyb,
                                       lkp, is_h, pathd, lkgp, wgp, sp2, sp3, ringt,
                                       (float*)d_out);
}